// round 1
// baseline (speedup 1.0000x reference)
#include <cuda_runtime.h>

#define B_G 4096
#define L_N 256
#define HID 32
#define FIN 64

__global__ __launch_bounds__(256)
void snake_kernel(const float* __restrict__ x,
                  const float* __restrict__ heads,
                  const float* __restrict__ body_sizes,
                  const float* __restrict__ fruits,
                  const float* __restrict__ W1, const float* __restrict__ b1,
                  const float* __restrict__ W2, const float* __restrict__ b2,
                  const float* __restrict__ Wr, const float* __restrict__ br,
                  const float* __restrict__ Wa1, const float* __restrict__ ba1,
                  const float* __restrict__ Wa2, const float* __restrict__ ba2,
                  const float* __restrict__ Wc, const float* __restrict__ bc,
                  const float* __restrict__ Wp, const float* __restrict__ bp,
                  const float* __restrict__ Wv, const float* __restrict__ bv,
                  float* __restrict__ out)
{
    __shared__ float S[L_N][HID + 1];     // node features, padded stride 33
    __shared__ float sW2[HID * HID];
    __shared__ float sW1[2 * HID];
    __shared__ float sb1[HID], sb2[HID];
    __shared__ float P[8][HID];           // pooling partials
    __shared__ float pooledS[HID];
    __shared__ float auxS[HID];
    __shared__ float cinS[FIN];
    __shared__ float combS[FIN];

    const int b = blockIdx.x;
    const int t = threadIdx.x;

    // cooperative weight staging
    for (int i = t; i < HID * HID; i += 256) sW2[i] = W2[i];
    if (t < 2 * HID) sW1[t] = W1[t];
    if (t < HID) { sb1[t] = b1[t]; sb2[t] = b2[t]; }

    // node input (coalesced float2)
    const float2 xv = ((const float2*)x)[b * L_N + t];
    __syncthreads();

    // ---------------- layer 1: x @ W1 ----------------
    float acc[HID];
#pragma unroll
    for (int f = 0; f < HID; f++) acc[f] = xv.x * sW1[f] + xv.y * sW1[HID + f];
#pragma unroll
    for (int f = 0; f < HID; f++) S[t][f] = acc[f];
    __syncthreads();

    // chain-GCN stencil weights (deg: endpoints 2, interior 3, incl self-loop)
    const float rs2 = 0.70710678118654752440f;  // 1/sqrt(2)
    const float rs3 = 0.57735026918962576451f;  // 1/sqrt(3)
    const float dinv = (t == 0 || t == L_N - 1) ? rs2 : rs3;
    const float wl  = (t == 0)        ? 0.f : dinv * ((t == 1)       ? rs2 : rs3);
    const float wr  = (t == L_N - 1)  ? 0.f : dinv * ((t == L_N - 2) ? rs2 : rs3);
    const float wcc = dinv * dinv;
    const int tm = (t > 0)       ? t - 1 : 0;
    const int tp = (t < L_N - 1) ? t + 1 : L_N - 1;

#pragma unroll
    for (int f = 0; f < HID; f++) {
        float a = wcc * S[t][f] + wl * S[tm][f] + wr * S[tp][f] + sb1[f];
        acc[f] = fmaxf(a, 0.f);
    }
    __syncthreads();
#pragma unroll
    for (int f = 0; f < HID; f++) S[t][f] = acc[f];   // h1
    __syncthreads();

    // ---------------- layer 2: h1 @ W2 (32x32, float4 weight loads) ----------------
    float hw[HID];
#pragma unroll
    for (int f = 0; f < HID; f++) hw[f] = 0.f;
#pragma unroll
    for (int k = 0; k < HID; k++) {
        const float hk = S[t][k];
        const float4* w4 = (const float4*)(sW2 + k * HID);
#pragma unroll
        for (int q = 0; q < HID / 4; q++) {
            float4 w = w4[q];
            hw[4 * q + 0] += hk * w.x;
            hw[4 * q + 1] += hk * w.y;
            hw[4 * q + 2] += hk * w.z;
            hw[4 * q + 3] += hk * w.w;
        }
    }
    // same-row read->write by same thread: no sync needed before overwrite
#pragma unroll
    for (int f = 0; f < HID; f++) S[t][f] = hw[f];
    __syncthreads();

#pragma unroll
    for (int f = 0; f < HID; f++) {
        float a = wcc * S[t][f] + wl * S[tm][f] + wr * S[tp][f] + sb2[f];
        acc[f] = fmaxf(a, 0.f);
    }
    __syncthreads();
#pragma unroll
    for (int f = 0; f < HID; f++) S[t][f] = acc[f];   // h2
    __syncthreads();

    // ---------------- mean pool: column sums ----------------
    {
        const int f = t & 31, c = t >> 5;
        float s = 0.f;
#pragma unroll 8
        for (int r = 0; r < 32; r++) s += S[c * 32 + r][f];
        P[c][f] = s;
    }
    __syncthreads();

    if (t < HID) {
        float p = 0.f;
#pragma unroll
        for (int c = 0; c < 8; c++) p += P[c][t];
        pooledS[t] = p * (1.f / 256.f);

        // aux layer 1: [heads(2), body_size(1), fruits(2)] @ Wa1 + ba1
        const float h0 = heads[2 * b], h1v = heads[2 * b + 1];
        const float bs = body_sizes[b];
        const float fr0 = fruits[2 * b], fr1 = fruits[2 * b + 1];
        float a1 = ba1[t]
                 + h0  * Wa1[0 * HID + t]
                 + h1v * Wa1[1 * HID + t]
                 + bs  * Wa1[2 * HID + t]
                 + fr0 * Wa1[3 * HID + t]
                 + fr1 * Wa1[4 * HID + t];
        auxS[t] = fmaxf(a1, 0.f);
    }
    __syncthreads();

    if (t < HID) {
        float a2 = ba2[t];
#pragma unroll
        for (int k = 0; k < HID; k++) a2 += auxS[k] * Wa2[k * HID + t];
        a2 = fmaxf(a2, 0.f);
        float be = br[t];
#pragma unroll
        for (int k = 0; k < HID; k++) be += pooledS[k] * Wr[k * HID + t];
        cinS[t] = be;          // body_emb
        cinS[HID + t] = a2;    // aux
    }
    __syncthreads();

    if (t < FIN) {
        float c = bc[t];
#pragma unroll
        for (int k = 0; k < FIN; k++) c += cinS[k] * Wc[k * FIN + t];
        combS[t] = fmaxf(c, 0.f);
    }
    __syncthreads();

    if (t < 5) {
        float lg = bp[t];
#pragma unroll
        for (int k = 0; k < FIN; k++) lg += combS[k] * Wp[k * 5 + t];
        out[b * 5 + t] = lg;                      // logits [B,5]
    } else if (t == 5) {
        float v = bv[0];
#pragma unroll
        for (int k = 0; k < FIN; k++) v += combS[k] * Wv[k];
        out[B_G * 5 + b] = v;                     // value [B]
    }
}

extern "C" void kernel_launch(void* const* d_in, const int* in_sizes, int n_in,
                              void* d_out, int out_size) {
    const float* x          = (const float*)d_in[0];
    const float* heads      = (const float*)d_in[1];
    const float* body_sizes = (const float*)d_in[2];
    const float* fruits     = (const float*)d_in[3];
    const float* W1  = (const float*)d_in[4];
    const float* b1  = (const float*)d_in[5];
    const float* W2  = (const float*)d_in[6];
    const float* b2  = (const float*)d_in[7];
    const float* Wr  = (const float*)d_in[8];
    const float* br  = (const float*)d_in[9];
    const float* Wa1 = (const float*)d_in[10];
    const float* ba1 = (const float*)d_in[11];
    const float* Wa2 = (const float*)d_in[12];
    const float* ba2 = (const float*)d_in[13];
    const float* Wc  = (const float*)d_in[14];
    const float* bc  = (const float*)d_in[15];
    const float* Wp  = (const float*)d_in[16];
    const float* bp  = (const float*)d_in[17];
    const float* Wv  = (const float*)d_in[18];
    const float* bv  = (const float*)d_in[19];
    // d_in[20] = edge_index, d_in[21] = batch_ids: structure is static (chain), unused

    float* out = (float*)d_out;
    snake_kernel<<<B_G, L_N>>>(x, heads, body_sizes, fruits,
                               W1, b1, W2, b2, Wr, br,
                               Wa1, ba1, Wa2, ba2, Wc, bc,
                               Wp, bp, Wv, bv, out);
}

// round 2
// speedup vs baseline: 1.1979x; 1.1979x over previous
#include <cuda_runtime.h>

#define B_G 4096
#define L_N 256
#define HID 32
#define FIN 64
#define SROW 36   // padded row stride (floats): 16B-aligned, stride%32==4 -> conflict-free

typedef unsigned long long u64;

__device__ __forceinline__ u64 pack2(float a, float b) {
    u64 r; asm("mov.b64 %0, {%1, %2};" : "=l"(r) : "f"(a), "f"(b)); return r;
}
__device__ __forceinline__ void fma2(u64& d, u64 a, u64 b) {
    asm("fma.rn.f32x2 %0, %1, %2, %0;" : "+l"(d) : "l"(a), "l"(b));
}
__device__ __forceinline__ u64 mul2(u64 a, u64 b) {
    u64 r; asm("mul.rn.f32x2 %0, %1, %2;" : "=l"(r) : "l"(a), "l"(b)); return r;
}
__device__ __forceinline__ u64 add2(u64 a, u64 b) {
    u64 r; asm("add.rn.f32x2 %0, %1, %2;" : "=l"(r) : "l"(a), "l"(b)); return r;
}

__global__ __launch_bounds__(256, 3)
void snake_kernel(const float* __restrict__ x,
                  const float* __restrict__ heads,
                  const float* __restrict__ body_sizes,
                  const float* __restrict__ fruits,
                  const float* __restrict__ W1, const float* __restrict__ b1,
                  const float* __restrict__ W2, const float* __restrict__ b2,
                  const float* __restrict__ Wr, const float* __restrict__ br,
                  const float* __restrict__ Wa1, const float* __restrict__ ba1,
                  const float* __restrict__ Wa2, const float* __restrict__ ba2,
                  const float* __restrict__ Wc, const float* __restrict__ bc,
                  const float* __restrict__ Wp, const float* __restrict__ bp,
                  const float* __restrict__ Wv, const float* __restrict__ bv,
                  float* __restrict__ out)
{
    __shared__ __align__(16) float S[L_N * SROW];      // 36 KB node features
    __shared__ __align__(16) float sW2[HID * HID];     // 4 KB
    __shared__ __align__(16) float sW1[2 * HID];
    __shared__ __align__(16) float sb1[HID];
    __shared__ __align__(16) float sb2[HID];
    __shared__ __align__(16) float P[32 * 32];         // 4 KB pooling partials
    __shared__ float pooledS[HID];
    __shared__ float auxS[HID];
    __shared__ float cinS[FIN];
    __shared__ float combS[FIN];

    const int b = blockIdx.x;
    const int t = threadIdx.x;

    // ---- cooperative weight staging (vectorized) ----
    ((float4*)sW2)[t & 255] = ((const float4*)W2)[t & 255];
    if (t < 16) ((float4*)sW1)[t] = ((const float4*)W1)[t];
    if (t < 8)  ((float4*)sb1)[t] = ((const float4*)b1)[t];
    else if (t < 16) ((float4*)sb2)[t - 8] = ((const float4*)b2)[t - 8];

    const float2 xv = ((const float2*)x)[b * L_N + t];
    __syncthreads();

    // ---------------- layer 1: x @ W1 (packed f32x2) ----------------
    {
        const u64 xp0 = pack2(xv.x, xv.x);
        const u64 xp1 = pack2(xv.y, xv.y);
        const u64* w1a = (const u64*)sW1;          // row 0 of W1, 16 pairs
        const u64* w1b = (const u64*)(sW1 + HID);  // row 1
        u64* dst = (u64*)&S[t * SROW];
#pragma unroll
        for (int p = 0; p < 16; p++) {
            u64 a = mul2(xp0, w1a[p]);
            fma2(a, xp1, w1b[p]);
            dst[p] = a;                            // 8x STS.128 (pairs coalesce)
        }
    }
    __syncthreads();

    // ---- chain-GCN stencil weights (deg 2 at ends, 3 interior, incl self) ----
    const float rs2 = 0.70710678118654752440f;
    const float rs3 = 0.57735026918962576451f;
    const float dinv = (t == 0 || t == L_N - 1) ? rs2 : rs3;
    const float wl  = (t == 0)       ? 0.f : dinv * ((t == 1)       ? rs2 : rs3);
    const float wr  = (t == L_N - 1) ? 0.f : dinv * ((t == L_N - 2) ? rs2 : rs3);
    const float wcc = dinv * dinv;
    const int tm = (t > 0)       ? t - 1 : 0;
    const int tp = (t < L_N - 1) ? t + 1 : L_N - 1;

    // ---------------- stencil 1 + bias + relu ----------------
    float4 o[8];
#pragma unroll
    for (int q = 0; q < 8; q++) {
        float4 Lq = *(const float4*)&S[tm * SROW + 4 * q];
        float4 Cq = *(const float4*)&S[t  * SROW + 4 * q];
        float4 Rq = *(const float4*)&S[tp * SROW + 4 * q];
        float4 Bq = *(const float4*)&sb1[4 * q];
        o[q].x = fmaxf(fmaf(wcc, Cq.x, fmaf(wl, Lq.x, fmaf(wr, Rq.x, Bq.x))), 0.f);
        o[q].y = fmaxf(fmaf(wcc, Cq.y, fmaf(wl, Lq.y, fmaf(wr, Rq.y, Bq.y))), 0.f);
        o[q].z = fmaxf(fmaf(wcc, Cq.z, fmaf(wl, Lq.z, fmaf(wr, Rq.z, Bq.z))), 0.f);
        o[q].w = fmaxf(fmaf(wcc, Cq.w, fmaf(wl, Lq.w, fmaf(wr, Rq.w, Bq.w))), 0.f);
    }
    __syncthreads();
#pragma unroll
    for (int q = 0; q < 8; q++) *(float4*)&S[t * SROW + 4 * q] = o[q];  // h1
    __syncthreads();

    // ---------------- layer 2 GEMM: 4 rows x 8 cols per thread, f32x2 ----------------
    const int r  = t & 63;      // row base; owns rows r + 64*i
    const int cg = t >> 6;      // column group: cols 8*cg .. 8*cg+7
    u64 accp[4][4];
#pragma unroll
    for (int i = 0; i < 4; i++)
#pragma unroll
        for (int p = 0; p < 4; p++) accp[i][p] = 0ull;

#pragma unroll
    for (int kb = 0; kb < 8; kb++) {
        float4 h4[4];
#pragma unroll
        for (int i = 0; i < 4; i++)
            h4[i] = *(const float4*)&S[(r + 64 * i) * SROW + 4 * kb];
#pragma unroll
        for (int kk = 0; kk < 4; kk++) {
            const int k = 4 * kb + kk;
            const ulonglong2* wp = (const ulonglong2*)&sW2[k * HID + 8 * cg];
            ulonglong2 wA = wp[0];   // col pairs (0,1),(2,3) of slab
            ulonglong2 wB = wp[1];   // col pairs (4,5),(6,7)
#pragma unroll
            for (int i = 0; i < 4; i++) {
                float h = (kk == 0) ? h4[i].x : (kk == 1) ? h4[i].y
                        : (kk == 2) ? h4[i].z : h4[i].w;
                u64 hp = pack2(h, h);
                fma2(accp[i][0], hp, wA.x);
                fma2(accp[i][1], hp, wA.y);
                fma2(accp[i][2], hp, wB.x);
                fma2(accp[i][3], hp, wB.y);
            }
        }
    }
    __syncthreads();   // all h1 reads done before overwrite
#pragma unroll
    for (int i = 0; i < 4; i++) {
        float* dst = &S[(r + 64 * i) * SROW + 8 * cg];
        ((ulonglong2*)dst)[0] = make_ulonglong2(accp[i][0], accp[i][1]);
        ((ulonglong2*)dst)[1] = make_ulonglong2(accp[i][2], accp[i][3]);
    }
    __syncthreads();

    // ---------------- stencil 2 + bias + relu ----------------
#pragma unroll
    for (int q = 0; q < 8; q++) {
        float4 Lq = *(const float4*)&S[tm * SROW + 4 * q];
        float4 Cq = *(const float4*)&S[t  * SROW + 4 * q];
        float4 Rq = *(const float4*)&S[tp * SROW + 4 * q];
        float4 Bq = *(const float4*)&sb2[4 * q];
        o[q].x = fmaxf(fmaf(wcc, Cq.x, fmaf(wl, Lq.x, fmaf(wr, Rq.x, Bq.x))), 0.f);
        o[q].y = fmaxf(fmaf(wcc, Cq.y, fmaf(wl, Lq.y, fmaf(wr, Rq.y, Bq.y))), 0.f);
        o[q].z = fmaxf(fmaf(wcc, Cq.z, fmaf(wl, Lq.z, fmaf(wr, Rq.z, Bq.z))), 0.f);
        o[q].w = fmaxf(fmaf(wcc, Cq.w, fmaf(wl, Lq.w, fmaf(wr, Rq.w, Bq.w))), 0.f);
    }
    __syncthreads();
#pragma unroll
    for (int q = 0; q < 8; q++) *(float4*)&S[t * SROW + 4 * q] = o[q];  // h2
    __syncthreads();

    // ---------------- mean pool: two-stage column sums ----------------
    {
        const int g = t >> 3;   // row group 0..31 (8 rows each)
        const int q = t & 7;    // float4 chunk
        u64 s0 = 0ull, s1 = 0ull;
#pragma unroll
        for (int rr = 0; rr < 8; rr++) {
            ulonglong2 v = *(const ulonglong2*)&S[(g * 8 + rr) * SROW + 4 * q];
            s0 = add2(s0, v.x);
            s1 = add2(s1, v.y);
        }
        *(ulonglong2*)&P[g * 32 + 4 * q] = make_ulonglong2(s0, s1);
    }
    __syncthreads();

    if (t < HID) {
        float p = 0.f;
#pragma unroll
        for (int g = 0; g < 32; g++) p += P[g * 32 + t];
        pooledS[t] = p * (1.f / 256.f);

        // aux layer 1
        const float h0 = heads[2 * b], h1v = heads[2 * b + 1];
        const float bs = body_sizes[b];
        const float fr0 = fruits[2 * b], fr1 = fruits[2 * b + 1];
        float a1 = ba1[t]
                 + h0  * Wa1[0 * HID + t]
                 + h1v * Wa1[1 * HID + t]
                 + bs  * Wa1[2 * HID + t]
                 + fr0 * Wa1[3 * HID + t]
                 + fr1 * Wa1[4 * HID + t];
        auxS[t] = fmaxf(a1, 0.f);
    }
    __syncthreads();

    if (t < HID) {
        float a2 = ba2[t];
#pragma unroll
        for (int k = 0; k < HID; k++) a2 += auxS[k] * Wa2[k * HID + t];
        a2 = fmaxf(a2, 0.f);
        float be = br[t];
#pragma unroll
        for (int k = 0; k < HID; k++) be += pooledS[k] * Wr[k * HID + t];
        cinS[t] = be;          // body_emb
        cinS[HID + t] = a2;    // aux
    }
    __syncthreads();

    if (t < FIN) {
        float c = bc[t];
#pragma unroll
        for (int k = 0; k < FIN; k++) c += cinS[k] * Wc[k * FIN + t];
        combS[t] = fmaxf(c, 0.f);
    }
    __syncthreads();

    if (t < 5) {
        float lg = bp[t];
#pragma unroll
        for (int k = 0; k < FIN; k++) lg += combS[k] * Wp[k * 5 + t];
        out[b * 5 + t] = lg;                      // logits [B,5]
    } else if (t == 5) {
        float v = bv[0];
#pragma unroll
        for (int k = 0; k < FIN; k++) v += combS[k] * Wv[k];
        out[B_G * 5 + b] = v;                     // value [B]
    }
}

extern "C" void kernel_launch(void* const* d_in, const int* in_sizes, int n_in,
                              void* d_out, int out_size) {
    const float* x          = (const float*)d_in[0];
    const float* heads      = (const float*)d_in[1];
    const float* body_sizes = (const float*)d_in[2];
    const float* fruits     = (const float*)d_in[3];
    const float* W1  = (const float*)d_in[4];
    const float* b1  = (const float*)d_in[5];
    const float* W2  = (const float*)d_in[6];
    const float* b2  = (const float*)d_in[7];
    const float* Wr  = (const float*)d_in[8];
    const float* br  = (const float*)d_in[9];
    const float* Wa1 = (const float*)d_in[10];
    const float* ba1 = (const float*)d_in[11];
    const float* Wa2 = (const float*)d_in[12];
    const float* ba2 = (const float*)d_in[13];
    const float* Wc  = (const float*)d_in[14];
    const float* bc  = (const float*)d_in[15];
    const float* Wp  = (const float*)d_in[16];
    const float* bp  = (const float*)d_in[17];
    const float* Wv  = (const float*)d_in[18];
    const float* bv  = (const float*)d_in[19];
    // d_in[20] = edge_index, d_in[21] = batch_ids: static chain structure, unused

    float* out = (float*)d_out;
    snake_kernel<<<B_G, L_N>>>(x, heads, body_sizes, fruits,
                               W1, b1, W2, b2, Wr, br,
                               Wa1, ba1, Wa2, ba2, Wc, bc,
                               Wp, bp, Wv, bv, out);
}

// round 3
// speedup vs baseline: 1.3929x; 1.1628x over previous
#include <cuda_runtime.h>

#define B_G 4096
#define HID 32
#define FIN 64
#define PROW 36   // padded pool row stride

typedef unsigned long long u64;

__device__ __forceinline__ u64 pack2(float a, float b) {
    u64 r; asm("mov.b64 %0, {%1, %2};" : "=l"(r) : "f"(a), "f"(b)); return r;
}
__device__ __forceinline__ void unpack2(float& a, float& b, u64 v) {
    asm("mov.b64 {%0, %1}, %2;" : "=f"(a), "=f"(b) : "l"(v));
}
__device__ __forceinline__ void fma2(u64& d, u64 a, u64 b) {
    asm("fma.rn.f32x2 %0, %1, %2, %0;" : "+l"(d) : "l"(a), "l"(b));
}
__device__ __forceinline__ u64 mul2(u64 a, u64 b) {
    u64 r; asm("mul.rn.f32x2 %0, %1, %2;" : "=l"(r) : "l"(a), "l"(b)); return r;
}

__global__ __launch_bounds__(128, 3)
void snake_kernel(const float* __restrict__ x,
                  const float* __restrict__ heads,
                  const float* __restrict__ body_sizes,
                  const float* __restrict__ fruits,
                  const float* __restrict__ W1, const float* __restrict__ b1,
                  const float* __restrict__ W2, const float* __restrict__ b2,
                  const float* __restrict__ Wr, const float* __restrict__ br,
                  const float* __restrict__ Wa1, const float* __restrict__ ba1,
                  const float* __restrict__ Wa2, const float* __restrict__ ba2,
                  const float* __restrict__ Wc, const float* __restrict__ bc,
                  const float* __restrict__ Wp, const float* __restrict__ bp,
                  const float* __restrict__ Wv, const float* __restrict__ bv,
                  float* __restrict__ out)
{
    __shared__ __align__(16) float sW2[HID * HID];        // 4 KB
    __shared__ __align__(16) float sW1[2 * HID];
    __shared__ __align__(16) float sb1[HID];
    __shared__ __align__(16) float sb2[HID];
    __shared__ __align__(16) float edgeA[4][HID];         // last node row per warp
    __shared__ __align__(16) float edgeB[4][HID];         // first node row per warp
    __shared__ __align__(16) float P[128 * PROW];         // 18 KB pool partials
    __shared__ float P2[128];
    __shared__ float pooledS[HID];
    __shared__ float auxS[HID];
    __shared__ float cinS[FIN];
    __shared__ float combS[FIN];

    const int b = blockIdx.x;
    const int t = threadIdx.x;
    const int lane = t & 31;
    const int w = t >> 5;

    // ---- weight staging ----
    ((float4*)sW2)[t] = ((const float4*)W2)[t];
    ((float4*)sW2)[t + 128] = ((const float4*)W2)[t + 128];
    if (t < 16) ((float4*)sW1)[t] = ((const float4*)W1)[t];
    else if (t < 24) ((float4*)sb1)[t - 16] = ((const float4*)b1)[t - 16];
    else if (t < 32) ((float4*)sb2)[t - 24] = ((const float4*)b2)[t - 24];

    // node inputs: thread owns nodes 2t (n0) and 2t+1 (n1)
    const float4 xv = ((const float4*)x)[b * 128 + t];
    __syncthreads();

    // ---------------- layer 1: y = x @ W1 (registers) ----------------
    float y0[HID], y1[HID];
    {
        const u64* w1a = (const u64*)sW1;
        const u64* w1b = (const u64*)(sW1 + HID);
        const u64 xa0 = pack2(xv.x, xv.x), xb0 = pack2(xv.y, xv.y);
        const u64 xa1 = pack2(xv.z, xv.z), xb1 = pack2(xv.w, xv.w);
#pragma unroll
        for (int p = 0; p < 16; p++) {
            const u64 wA = w1a[p], wB = w1b[p];
            u64 v0 = mul2(xa0, wA); fma2(v0, xb0, wB);
            u64 v1 = mul2(xa1, wA); fma2(v1, xb1, wB);
            unpack2(y0[2 * p], y0[2 * p + 1], v0);
            unpack2(y1[2 * p], y1[2 * p + 1], v1);
        }
    }

    // ---- chain GCN stencil weights (node i0=2t, i1=2t+1; L=256) ----
    const float rs2 = 0.70710678118654752440f;
    const float rs3 = 0.57735026918962576451f;
    const float dinv0 = (t == 0)   ? rs2 : rs3;
    const float dinv1 = (t == 127) ? rs2 : rs3;
    const float wc0 = dinv0 * dinv0;
    const float wc1 = dinv1 * dinv1;
    const float wl0 = (t == 0)   ? 0.f : dinv0 * rs3;              // nbr 2t-1 interior
    const float wr0 = dinv0 * ((t == 127) ? rs2 : rs3);            // nbr 2t+1
    const float wl1 = dinv1 * ((t == 0) ? rs2 : rs3);              // nbr 2t
    const float wr1 = (t == 127) ? 0.f : dinv1 * rs3;              // nbr 2t+2 interior
    const int wprev = (w + 3) & 3;   // clamped/wrapped; guarded by wl0=0 at t==0
    const int wnext = (w + 1) & 3;   // guarded by wr1=0 at t==127

#define STENCIL(BIAS)                                                         \
    {                                                                         \
        if (lane == 31) {                                                     \
            _Pragma("unroll")                                                 \
            for (int q = 0; q < 8; q++)                                       \
                *(float4*)&edgeA[w][4 * q] = make_float4(                     \
                    y1[4 * q], y1[4 * q + 1], y1[4 * q + 2], y1[4 * q + 3]);  \
        }                                                                     \
        if (lane == 0) {                                                      \
            _Pragma("unroll")                                                 \
            for (int q = 0; q < 8; q++)                                       \
                *(float4*)&edgeB[w][4 * q] = make_float4(                     \
                    y0[4 * q], y0[4 * q + 1], y0[4 * q + 2], y0[4 * q + 3]);  \
        }                                                                     \
        __syncthreads();                                                      \
        _Pragma("unroll")                                                     \
        for (int f = 0; f < HID; f++) {                                       \
            float up = __shfl_up_sync(0xffffffffu, y1[f], 1);                 \
            float pv = (lane == 0) ? edgeA[wprev][f] : up;                    \
            float dn = __shfl_down_sync(0xffffffffu, y0[f], 1);               \
            float nx = (lane == 31) ? edgeB[wnext][f] : dn;                   \
            float bf = (BIAS)[f];                                             \
            float a0 = fmaf(wc0, y0[f], fmaf(wl0, pv,    fmaf(wr0, y1[f], bf))); \
            float a1 = fmaf(wc1, y1[f], fmaf(wl1, y0[f], fmaf(wr1, nx,    bf))); \
            y0[f] = fmaxf(a0, 0.f);                                           \
            y1[f] = fmaxf(a1, 0.f);                                           \
        }                                                                     \
        __syncthreads();                                                      \
    }

    // ---------------- stencil 1 + relu (y -> h1, in place) ----------------
    STENCIL(sb1)

    // ---------------- layer 2 GEMM: z = h1 @ W2 (h in regs, W broadcast) ----
    u64 acc0[16], acc1[16];
#pragma unroll
    for (int p = 0; p < 16; p++) { acc0[p] = 0ull; acc1[p] = 0ull; }
#pragma unroll
    for (int k = 0; k < HID; k++) {
        const ulonglong2* wrow = (const ulonglong2*)&sW2[k * HID];
        const u64 h0p = pack2(y0[k], y0[k]);
        const u64 h1p = pack2(y1[k], y1[k]);
#pragma unroll
        for (int j = 0; j < 4; j++) {
            ulonglong2 wa = wrow[2 * j];
            ulonglong2 wb = wrow[2 * j + 1];
            fma2(acc0[4 * j + 0], h0p, wa.x);
            fma2(acc0[4 * j + 1], h0p, wa.y);
            fma2(acc0[4 * j + 2], h0p, wb.x);
            fma2(acc0[4 * j + 3], h0p, wb.y);
            fma2(acc1[4 * j + 0], h1p, wa.x);
            fma2(acc1[4 * j + 1], h1p, wa.y);
            fma2(acc1[4 * j + 2], h1p, wb.x);
            fma2(acc1[4 * j + 3], h1p, wb.y);
        }
    }
#pragma unroll
    for (int p = 0; p < 16; p++) {
        unpack2(y0[2 * p], y0[2 * p + 1], acc0[p]);
        unpack2(y1[2 * p], y1[2 * p + 1], acc1[p]);
    }

    // ---------------- stencil 2 + relu (y -> h2, in place) ----------------
    STENCIL(sb2)

    // ---------------- mean pool ----------------
#pragma unroll
    for (int q = 0; q < 8; q++)
        *(float4*)&P[t * PROW + 4 * q] = make_float4(
            y0[4 * q] + y1[4 * q], y0[4 * q + 1] + y1[4 * q + 1],
            y0[4 * q + 2] + y1[4 * q + 2], y0[4 * q + 3] + y1[4 * q + 3]);
    __syncthreads();
    {
        const int f = t & 31, g = t >> 5;
        float ps = 0.f;
#pragma unroll
        for (int r = 0; r < 32; r++) ps += P[(32 * g + r) * PROW + f];
        P2[g * 32 + f] = ps;
    }
    __syncthreads();

    if (t < HID) {
        pooledS[t] = (P2[t] + P2[32 + t] + P2[64 + t] + P2[96 + t]) * (1.f / 256.f);
        // aux layer 1
        const float h0 = heads[2 * b], h1v = heads[2 * b + 1];
        const float bs = body_sizes[b];
        const float fr0 = fruits[2 * b], fr1 = fruits[2 * b + 1];
        float a1 = ba1[t]
                 + h0  * Wa1[0 * HID + t]
                 + h1v * Wa1[1 * HID + t]
                 + bs  * Wa1[2 * HID + t]
                 + fr0 * Wa1[3 * HID + t]
                 + fr1 * Wa1[4 * HID + t];
        auxS[t] = fmaxf(a1, 0.f);
    }
    __syncthreads();

    if (t < HID) {
        float a2 = ba2[t];
#pragma unroll
        for (int k = 0; k < HID; k++) a2 += auxS[k] * Wa2[k * HID + t];
        a2 = fmaxf(a2, 0.f);
        float be = br[t];
#pragma unroll
        for (int k = 0; k < HID; k++) be += pooledS[k] * Wr[k * HID + t];
        cinS[t] = be;          // body_emb
        cinS[HID + t] = a2;    // aux
    }
    __syncthreads();

    if (t < FIN) {
        float c = bc[t];
#pragma unroll
        for (int k = 0; k < FIN; k++) c += cinS[k] * Wc[k * FIN + t];
        combS[t] = fmaxf(c, 0.f);
    }
    __syncthreads();

    if (t < 5) {
        float lg = bp[t];
#pragma unroll
        for (int k = 0; k < FIN; k++) lg += combS[k] * Wp[k * 5 + t];
        out[b * 5 + t] = lg;                      // logits [B,5]
    } else if (t == 5) {
        float v = bv[0];
#pragma unroll
        for (int k = 0; k < FIN; k++) v += combS[k] * Wv[k];
        out[B_G * 5 + b] = v;                     // value [B]
    }
}

extern "C" void kernel_launch(void* const* d_in, const int* in_sizes, int n_in,
                              void* d_out, int out_size) {
    const float* x          = (const float*)d_in[0];
    const float* heads      = (const float*)d_in[1];
    const float* body_sizes = (const float*)d_in[2];
    const float* fruits     = (const float*)d_in[3];
    const float* W1  = (const float*)d_in[4];
    const float* b1  = (const float*)d_in[5];
    const float* W2  = (const float*)d_in[6];
    const float* b2  = (const float*)d_in[7];
    const float* Wr  = (const float*)d_in[8];
    const float* br  = (const float*)d_in[9];
    const float* Wa1 = (const float*)d_in[10];
    const float* ba1 = (const float*)d_in[11];
    const float* Wa2 = (const float*)d_in[12];
    const float* ba2 = (const float*)d_in[13];
    const float* Wc  = (const float*)d_in[14];
    const float* bc  = (const float*)d_in[15];
    const float* Wp  = (const float*)d_in[16];
    const float* bp  = (const float*)d_in[17];
    const float* Wv  = (const float*)d_in[18];
    const float* bv  = (const float*)d_in[19];
    // d_in[20] = edge_index, d_in[21] = batch_ids: static chain structure, unused

    float* out = (float*)d_out;
    snake_kernel<<<B_G, 128>>>(x, heads, body_sizes, fruits,
                               W1, b1, W2, b2, Wr, br,
                               Wa1, ba1, Wa2, ba2, Wc, bc,
                               Wp, bp, Wv, bv, out);
}

// round 4
// speedup vs baseline: 1.6238x; 1.1658x over previous
#include <cuda_runtime.h>

#define B_G 4096
#define HID 32
#define FIN 64
#define PROW 36

typedef unsigned long long u64;

__device__ __forceinline__ u64 pack2(float a, float b) {
    u64 r; asm("mov.b64 %0, {%1, %2};" : "=l"(r) : "f"(a), "f"(b)); return r;
}
__device__ __forceinline__ void unpack2(float& a, float& b, u64 v) {
    asm("mov.b64 {%0, %1}, %2;" : "=f"(a), "=f"(b) : "l"(v));
}
__device__ __forceinline__ void fma2(u64& d, u64 a, u64 b) {
    asm("fma.rn.f32x2 %0, %1, %2, %0;" : "+l"(d) : "l"(a), "l"(b));
}
__device__ __forceinline__ u64 mul2(u64 a, u64 b) {
    u64 r; asm("mul.rn.f32x2 %0, %1, %2;" : "=l"(r) : "l"(a), "l"(b)); return r;
}

__global__ __launch_bounds__(128, 4)
void snake_kernel(const float* __restrict__ x,
                  const float* __restrict__ heads,
                  const float* __restrict__ body_sizes,
                  const float* __restrict__ fruits,
                  const float* __restrict__ W1, const float* __restrict__ b1,
                  const float* __restrict__ W2, const float* __restrict__ b2,
                  const float* __restrict__ Wr, const float* __restrict__ br,
                  const float* __restrict__ Wa1, const float* __restrict__ ba1,
                  const float* __restrict__ Wa2, const float* __restrict__ ba2,
                  const float* __restrict__ Wc, const float* __restrict__ bc,
                  const float* __restrict__ Wp, const float* __restrict__ bp,
                  const float* __restrict__ Wv, const float* __restrict__ bv,
                  float* __restrict__ out)
{
    __shared__ __align__(16) float sW2[HID * HID];     // 4 KB
    __shared__ __align__(16) float sW1[2 * HID];
    __shared__ __align__(16) float sb1[HID];
    __shared__ __align__(16) float sb2[HID];
    __shared__ __align__(16) u64 edgeA[2][4][16];      // stage-parity double buffer
    __shared__ __align__(16) u64 edgeB[2][4][16];
    __shared__ __align__(16) float P[128 * PROW];      // 18 KB pool partials
    __shared__ float P2[128];
    __shared__ float pooledS[HID];
    __shared__ float auxS[HID];
    __shared__ float cinS[FIN];
    __shared__ float combS[FIN];

    const int b = blockIdx.x;
    const int t = threadIdx.x;
    const int lane = t & 31;
    const int w = t >> 5;

    // ---- weight staging ----
    ((float4*)sW2)[t] = ((const float4*)W2)[t];
    ((float4*)sW2)[t + 128] = ((const float4*)W2)[t + 128];
    if (t < 16) ((float4*)sW1)[t] = ((const float4*)W1)[t];
    else if (t < 24) ((float4*)sb1)[t - 16] = ((const float4*)b1)[t - 16];
    else if (t < 32) ((float4*)sb2)[t - 24] = ((const float4*)b2)[t - 24];

    const float4 xv = ((const float4*)x)[b * 128 + t];
    __syncthreads();

    // ---------------- layer 1: y = x @ W1 ----------------
    float y0[HID], y1[HID];
    {
        const u64* w1a = (const u64*)sW1;
        const u64* w1b = (const u64*)(sW1 + HID);
        const u64 xa0 = pack2(xv.x, xv.x), xb0 = pack2(xv.y, xv.y);
        const u64 xa1 = pack2(xv.z, xv.z), xb1 = pack2(xv.w, xv.w);
#pragma unroll
        for (int p = 0; p < 16; p++) {
            const u64 wA = w1a[p], wB = w1b[p];
            u64 v0 = mul2(xa0, wA); fma2(v0, xb0, wB);
            u64 v1 = mul2(xa1, wA); fma2(v1, xb1, wB);
            unpack2(y0[2 * p], y0[2 * p + 1], v0);
            unpack2(y1[2 * p], y1[2 * p + 1], v1);
        }
    }

    // ---- chain GCN stencil weights (nodes 2t, 2t+1; L=256) ----
    const float rs2 = 0.70710678118654752440f;
    const float rs3 = 0.57735026918962576451f;
    const float dinv0 = (t == 0)   ? rs2 : rs3;
    const float dinv1 = (t == 127) ? rs2 : rs3;
    const float wc0 = dinv0 * dinv0;
    const float wc1 = dinv1 * dinv1;
    const float wl0 = (t == 0)   ? 0.f : dinv0 * rs3;
    const float wr0 = dinv0 * ((t == 127) ? rs2 : rs3);
    const float wl1 = dinv1 * ((t == 0) ? rs2 : rs3);
    const float wr1 = (t == 127) ? 0.f : dinv1 * rs3;
    const int wprev = (w + 3) & 3;
    const int wnext = (w + 1) & 3;

    // ---------------- stencil 1 + relu (stage 0, scalar) ----------------
    {
        if (lane == 31) {
            u64* ea = edgeA[0][w];
#pragma unroll
            for (int p = 0; p < 16; p++) ea[p] = pack2(y1[2 * p], y1[2 * p + 1]);
        }
        if (lane == 0) {
            u64* eb = edgeB[0][w];
#pragma unroll
            for (int p = 0; p < 16; p++) eb[p] = pack2(y0[2 * p], y0[2 * p + 1]);
        }
        __syncthreads();
#pragma unroll
        for (int f = 0; f < HID; f++) {
            float up = __shfl_up_sync(0xffffffffu, y1[f], 1);
            float pv, nv;
            if (lane == 0) { float a, bb; unpack2(a, bb, edgeA[0][wprev][f >> 1]); pv = (f & 1) ? bb : a; }
            else pv = up;
            float dn = __shfl_down_sync(0xffffffffu, y0[f], 1);
            if (lane == 31) { float a, bb; unpack2(a, bb, edgeB[0][wnext][f >> 1]); nv = (f & 1) ? bb : a; }
            else nv = dn;
            float bf = sb1[f];
            float a0 = fmaf(wc0, y0[f], fmaf(wl0, pv,    fmaf(wr0, y1[f], bf)));
            float a1 = fmaf(wc1, y1[f], fmaf(wl1, y0[f], fmaf(wr1, nv,    bf)));
            y0[f] = fmaxf(a0, 0.f);
            y1[f] = fmaxf(a1, 0.f);
        }
    }

    // packed stencil weights for the halves
    const u64 wc0p = pack2(wc0, wc0), wc1p = pack2(wc1, wc1);
    const u64 wl0p = pack2(wl0, wl0), wr0p = pack2(wr0, wr0);
    const u64 wl1p = pack2(wl1, wl1), wr1p = pack2(wr1, wr1);
    const u64* b2p = (const u64*)sb2;

    // ---------------- layer 2 GEMM + stencil 2 + pool, two 16-col halves ----
#pragma unroll 1
    for (int h = 0; h < 2; h++) {
        const int ho = h * 16;          // float column offset
        const int sp = 1 - h;           // edge stage parity (stencil1 used 0)

        u64 acc0[8], acc1[8];
#pragma unroll
        for (int p = 0; p < 8; p++) { acc0[p] = 0ull; acc1[p] = 0ull; }

#pragma unroll
        for (int k = 0; k < HID; k++) {
            const ulonglong2* wr2 = (const ulonglong2*)&sW2[k * HID + ho];
            ulonglong2 wq0 = wr2[0], wq1 = wr2[1], wq2 = wr2[2], wq3 = wr2[3];
            const u64 h0p = pack2(y0[k], y0[k]);
            const u64 h1p = pack2(y1[k], y1[k]);
            fma2(acc0[0], h0p, wq0.x); fma2(acc0[1], h0p, wq0.y);
            fma2(acc0[2], h0p, wq1.x); fma2(acc0[3], h0p, wq1.y);
            fma2(acc0[4], h0p, wq2.x); fma2(acc0[5], h0p, wq2.y);
            fma2(acc0[6], h0p, wq3.x); fma2(acc0[7], h0p, wq3.y);
            fma2(acc1[0], h1p, wq0.x); fma2(acc1[1], h1p, wq0.y);
            fma2(acc1[2], h1p, wq1.x); fma2(acc1[3], h1p, wq1.y);
            fma2(acc1[4], h1p, wq2.x); fma2(acc1[5], h1p, wq2.y);
            fma2(acc1[6], h1p, wq3.x); fma2(acc1[7], h1p, wq3.y);
        }

        // stencil 2 on packed accumulators + relu + pool partial
        if (lane == 31) {
            u64* ea = edgeA[sp][w];
#pragma unroll
            for (int p = 0; p < 8; p++) ea[p] = acc1[p];
        }
        if (lane == 0) {
            u64* eb = edgeB[sp][w];
#pragma unroll
            for (int p = 0; p < 8; p++) eb[p] = acc0[p];
        }
        __syncthreads();

        float part[16];
#pragma unroll
        for (int p = 0; p < 8; p++) {
            u64 up = __shfl_up_sync(0xffffffffu, acc1[p], 1);
            u64 pv = (lane == 0) ? edgeA[sp][wprev][p] : up;
            u64 dn = __shfl_down_sync(0xffffffffu, acc0[p], 1);
            u64 nx = (lane == 31) ? edgeB[sp][wnext][p] : dn;
            u64 a0 = b2p[h * 8 + p];
            u64 a1 = a0;
            fma2(a0, wc0p, acc0[p]); fma2(a0, wl0p, pv);      fma2(a0, wr0p, acc1[p]);
            fma2(a1, wc1p, acc1[p]); fma2(a1, wl1p, acc0[p]); fma2(a1, wr1p, nx);
            float r0a, r0b, r1a, r1b;
            unpack2(r0a, r0b, a0);
            unpack2(r1a, r1b, a1);
            part[2 * p]     = fmaxf(r0a, 0.f) + fmaxf(r1a, 0.f);
            part[2 * p + 1] = fmaxf(r0b, 0.f) + fmaxf(r1b, 0.f);
        }
#pragma unroll
        for (int q = 0; q < 4; q++)
            *(float4*)&P[t * PROW + ho + 4 * q] =
                make_float4(part[4 * q], part[4 * q + 1], part[4 * q + 2], part[4 * q + 3]);
    }
    __syncthreads();

    // ---------------- pool reduction ----------------
    {
        const int f = t & 31, g = t >> 5;
        float ps = 0.f;
#pragma unroll
        for (int r = 0; r < 32; r++) ps += P[(32 * g + r) * PROW + f];
        P2[g * 32 + f] = ps;
    }
    __syncthreads();

    if (t < HID) {
        pooledS[t] = (P2[t] + P2[32 + t] + P2[64 + t] + P2[96 + t]) * (1.f / 256.f);
        const float h0 = heads[2 * b], h1v = heads[2 * b + 1];
        const float bs = body_sizes[b];
        const float fr0 = fruits[2 * b], fr1 = fruits[2 * b + 1];
        float a1 = ba1[t]
                 + h0  * Wa1[0 * HID + t]
                 + h1v * Wa1[1 * HID + t]
                 + bs  * Wa1[2 * HID + t]
                 + fr0 * Wa1[3 * HID + t]
                 + fr1 * Wa1[4 * HID + t];
        auxS[t] = fmaxf(a1, 0.f);
    }
    __syncthreads();

    if (t < HID) {
        float a2 = ba2[t];
#pragma unroll
        for (int k = 0; k < HID; k++) a2 += auxS[k] * Wa2[k * HID + t];
        a2 = fmaxf(a2, 0.f);
        float be = br[t];
#pragma unroll
        for (int k = 0; k < HID; k++) be += pooledS[k] * Wr[k * HID + t];
        cinS[t] = be;
        cinS[HID + t] = a2;
    }
    __syncthreads();

    if (t < FIN) {
        float c = bc[t];
#pragma unroll
        for (int k = 0; k < FIN; k++) c += cinS[k] * Wc[k * FIN + t];
        combS[t] = fmaxf(c, 0.f);
    }
    __syncthreads();

    if (t < 5) {
        float lg = bp[t];
#pragma unroll
        for (int k = 0; k < FIN; k++) lg += combS[k] * Wp[k * 5 + t];
        out[b * 5 + t] = lg;                      // logits [B,5]
    } else if (t == 5) {
        float v = bv[0];
#pragma unroll
        for (int k = 0; k < FIN; k++) v += combS[k] * Wv[k];
        out[B_G * 5 + b] = v;                     // value [B]
    }
}

extern "C" void kernel_launch(void* const* d_in, const int* in_sizes, int n_in,
                              void* d_out, int out_size) {
    const float* x          = (const float*)d_in[0];
    const float* heads      = (const float*)d_in[1];
    const float* body_sizes = (const float*)d_in[2];
    const float* fruits     = (const float*)d_in[3];
    const float* W1  = (const float*)d_in[4];
    const float* b1  = (const float*)d_in[5];
    const float* W2  = (const float*)d_in[6];
    const float* b2  = (const float*)d_in[7];
    const float* Wr  = (const float*)d_in[8];
    const float* br  = (const float*)d_in[9];
    const float* Wa1 = (const float*)d_in[10];
    const float* ba1 = (const float*)d_in[11];
    const float* Wa2 = (const float*)d_in[12];
    const float* ba2 = (const float*)d_in[13];
    const float* Wc  = (const float*)d_in[14];
    const float* bc  = (const float*)d_in[15];
    const float* Wp  = (const float*)d_in[16];
    const float* bp  = (const float*)d_in[17];
    const float* Wv  = (const float*)d_in[18];
    const float* bv  = (const float*)d_in[19];
    // d_in[20] = edge_index, d_in[21] = batch_ids: static chain, unused

    float* out = (float*)d_out;
    snake_kernel<<<B_G, 128>>>(x, heads, body_sizes, fruits,
                               W1, b1, W2, b2, Wr, br,
                               Wa1, ba1, Wa2, ba2, Wc, bc,
                               Wp, bp, Wv, bv, out);
}

// round 5
// speedup vs baseline: 1.7928x; 1.1041x over previous
#include <cuda_runtime.h>

#define B_G 4096
#define HID 32
#define FIN 64

typedef unsigned long long u64;

__device__ __forceinline__ u64 pack2(float a, float b) {
    u64 r; asm("mov.b64 %0, {%1, %2};" : "=l"(r) : "f"(a), "f"(b)); return r;
}
__device__ __forceinline__ void unpack2(float& a, float& b, u64 v) {
    asm("mov.b64 {%0, %1}, %2;" : "=f"(a), "=f"(b) : "l"(v));
}
__device__ __forceinline__ void fma2(u64& d, u64 a, u64 b) {
    asm("fma.rn.f32x2 %0, %1, %2, %0;" : "+l"(d) : "l"(a), "l"(b));
}
__device__ __forceinline__ u64 mul2(u64 a, u64 b) {
    u64 r; asm("mul.rn.f32x2 %0, %1, %2;" : "=l"(r) : "l"(a), "l"(b)); return r;
}
__device__ __forceinline__ u64 add2(u64 a, u64 b) {
    u64 r; asm("add.rn.f32x2 %0, %1, %2;" : "=l"(r) : "l"(a), "l"(b)); return r;
}

// dynamic smem layout (bytes)
#define HT_OFF     0         // hT: 32 rows x 384 floats (12-float groups) = 49152
#define W2_OFF     49152     // 4 KB
#define W1_OFF     53248     // 256 B
#define B1_OFF     53504     // 128 B
#define B2_OFF     53632     // 128 B
#define EA_OFF     53760     // 4 warps x 16 u64 = 512 B
#define EB_OFF     54272     // 512 B
#define PL_OFF     54784     // pooled, 128 B
#define AX_OFF     54912     // aux, 128 B
#define CI_OFF     55040     // cin, 256 B
#define CB_OFF     55296     // comb, 256 B
#define SMEM_TOTAL 55552

__global__ __launch_bounds__(128, 4)
void snake_kernel(const float* __restrict__ x,
                  const float* __restrict__ heads,
                  const float* __restrict__ body_sizes,
                  const float* __restrict__ fruits,
                  const float* __restrict__ W1, const float* __restrict__ b1,
                  const float* __restrict__ W2, const float* __restrict__ b2,
                  const float* __restrict__ Wr, const float* __restrict__ br,
                  const float* __restrict__ Wa1, const float* __restrict__ ba1,
                  const float* __restrict__ Wa2, const float* __restrict__ ba2,
                  const float* __restrict__ Wc, const float* __restrict__ bc,
                  const float* __restrict__ Wp, const float* __restrict__ bp,
                  const float* __restrict__ Wv, const float* __restrict__ bv,
                  float* __restrict__ out)
{
    extern __shared__ __align__(16) char smem[];
    float* hT   = (float*)(smem + HT_OFF);
    float* sW2  = (float*)(smem + W2_OFF);
    float* sW1  = (float*)(smem + W1_OFF);
    float* sb1  = (float*)(smem + B1_OFF);
    float* sb2  = (float*)(smem + B2_OFF);
    u64*  edgeA = (u64*)(smem + EA_OFF);     // [warp][16]
    u64*  edgeB = (u64*)(smem + EB_OFF);
    float* pooledS = (float*)(smem + PL_OFF);
    float* auxS    = (float*)(smem + AX_OFF);
    float* cinS    = (float*)(smem + CI_OFF);
    float* combS   = (float*)(smem + CB_OFF);

    const int b = blockIdx.x;
    const int t = threadIdx.x;
    const int lane = t & 31;
    const int w = t >> 5;

    // ---- weight staging ----
    ((float4*)sW2)[t] = ((const float4*)W2)[t];
    ((float4*)sW2)[t + 128] = ((const float4*)W2)[t + 128];
    if (t < 16) ((float4*)sW1)[t] = ((const float4*)W1)[t];
    else if (t < 24) ((float4*)sb1)[t - 16] = ((const float4*)b1)[t - 16];
    else if (t < 32) ((float4*)sb2)[t - 24] = ((const float4*)b2)[t - 24];

    const float4 xv = ((const float4*)x)[b * 128 + t];
    __syncthreads();

    // ---------------- layer 1: y = x @ W1 (nodes 2t, 2t+1) ----------------
    float y0[HID], y1[HID];
    {
        const u64* w1a = (const u64*)sW1;
        const u64* w1b = (const u64*)(sW1 + HID);
        const u64 xa0 = pack2(xv.x, xv.x), xb0 = pack2(xv.y, xv.y);
        const u64 xa1 = pack2(xv.z, xv.z), xb1 = pack2(xv.w, xv.w);
#pragma unroll
        for (int p = 0; p < 16; p++) {
            const u64 wA = w1a[p], wB = w1b[p];
            u64 v0 = mul2(xa0, wA); fma2(v0, xb0, wB);
            u64 v1 = mul2(xa1, wA); fma2(v1, xb1, wB);
            unpack2(y0[2 * p], y0[2 * p + 1], v0);
            unpack2(y1[2 * p], y1[2 * p + 1], v1);
        }
    }

    // ---- stencil 1 weights (nodes 2t, 2t+1; L=256) ----
    const float rs2 = 0.70710678118654752440f;
    const float rs3 = 0.57735026918962576451f;
    const float dinv0 = (t == 0)   ? rs2 : rs3;
    const float dinv1 = (t == 127) ? rs2 : rs3;
    const float wc0 = dinv0 * dinv0;
    const float wc1 = dinv1 * dinv1;
    const float wl0 = (t == 0)   ? 0.f : dinv0 * rs3;
    const float wr0 = dinv0 * ((t == 127) ? rs2 : rs3);
    const float wl1 = dinv1 * ((t == 0) ? rs2 : rs3);
    const float wr1 = (t == 127) ? 0.f : dinv1 * rs3;
    const int wprev = (w + 3) & 3;
    const int wnext = (w + 1) & 3;

    // ---------------- stencil 1 + relu ----------------
    {
        if (lane == 31) {
            u64* ea = &edgeA[w * 16];
#pragma unroll
            for (int p = 0; p < 16; p++) ea[p] = pack2(y1[2 * p], y1[2 * p + 1]);
        }
        if (lane == 0) {
            u64* eb = &edgeB[w * 16];
#pragma unroll
            for (int p = 0; p < 16; p++) eb[p] = pack2(y0[2 * p], y0[2 * p + 1]);
        }
        __syncthreads();
#pragma unroll
        for (int f = 0; f < HID; f++) {
            float up = __shfl_up_sync(0xffffffffu, y1[f], 1);
            float pv, nv;
            if (lane == 0) { float a, bb; unpack2(a, bb, edgeA[wprev * 16 + (f >> 1)]); pv = (f & 1) ? bb : a; }
            else pv = up;
            float dn = __shfl_down_sync(0xffffffffu, y0[f], 1);
            if (lane == 31) { float a, bb; unpack2(a, bb, edgeB[wnext * 16 + (f >> 1)]); nv = (f & 1) ? bb : a; }
            else nv = dn;
            float bf = sb1[f];
            float a0 = fmaf(wc0, y0[f], fmaf(wl0, pv,    fmaf(wr0, y1[f], bf)));
            float a1 = fmaf(wc1, y1[f], fmaf(wl1, y0[f], fmaf(wr1, nv,    bf)));
            y0[f] = fmaxf(a0, 0.f);
            y1[f] = fmaxf(a1, 0.f);
        }
    }

    // ---------------- write h1 transposed: hT[k][node], 12-float groups ----
    {
        const int g = t >> 2;            // node group (2t)>>3
        const int j = (2 * t) & 7;       // slot within group
        u64* dst = (u64*)&hT[g * 12 + j];
#pragma unroll
        for (int k = 0; k < HID; k++)
            dst[0 + k * 192] = pack2(y0[k], y1[k]);   // 192 u64 = 384 floats per row
    }
    __syncthreads();

    // ---------------- layer 2 GEMM: warp w -> cols 8w..8w+7, lane -> nodes 8l..8l+7 ----
    const int cw = 8 * w;
    u64 zc[8][4];
#pragma unroll
    for (int j = 0; j < 8; j++)
#pragma unroll
        for (int p = 0; p < 4; p++) zc[j][p] = 0ull;

#pragma unroll 8
    for (int k = 0; k < HID; k++) {
        const ulonglong2 wA = *(const ulonglong2*)&sW2[k * HID + cw];
        const ulonglong2 wB = *(const ulonglong2*)&sW2[k * HID + cw + 4];
        const float* hp = &hT[k * 384 + lane * 12];
        const float4 ha = *(const float4*)hp;
        const float4 hb = *(const float4*)(hp + 4);
#pragma unroll
        for (int j = 0; j < 8; j++) {
            const float hs = (j < 4) ? ((j == 0) ? ha.x : (j == 1) ? ha.y : (j == 2) ? ha.z : ha.w)
                                     : ((j == 4) ? hb.x : (j == 5) ? hb.y : (j == 6) ? hb.z : hb.w);
            const u64 hpk = pack2(hs, hs);
            fma2(zc[j][0], hpk, wA.x);
            fma2(zc[j][1], hpk, wA.y);
            fma2(zc[j][2], hpk, wB.x);
            fma2(zc[j][3], hpk, wB.y);
        }
    }

    // ---------------- stencil 2 + relu + pool (warp-local) ----------------
    u64 pz[4], nz[4], bb2[4];
#pragma unroll
    for (int p = 0; p < 4; p++) {
        pz[p] = __shfl_up_sync(0xffffffffu, zc[7][p], 1);    // node 8l-1
        nz[p] = __shfl_down_sync(0xffffffffu, zc[0][p], 1);  // node 8l+8
        bb2[p] = ((const u64*)&sb2[cw])[p];
    }

    const float C13 = 1.f / 3.f;
    const float C12 = 0.5f;
    const float C23 = rs2 * rs3;
    float pool[8];
#pragma unroll
    for (int i = 0; i < 8; i++) pool[i] = 0.f;

#pragma unroll
    for (int j = 0; j < 8; j++) {
        float wcj = C13, wlj = C13, wrj = C13;
        if (lane == 0) {
            if (j == 0) { wcj = C12; wlj = 0.f; wrj = C23; }
            if (j == 1) { wlj = C23; }
        }
        if (lane == 31) {
            if (j == 7) { wcj = C12; wrj = 0.f; wlj = C23; }
            if (j == 6) { wrj = C23; }
        }
        const u64 wcp = pack2(wcj, wcj);
        const u64 wlp = pack2(wlj, wlj);
        const u64 wrp = pack2(wrj, wrj);
#pragma unroll
        for (int p = 0; p < 4; p++) {
            u64 left  = (j == 0) ? pz[p] : zc[j - 1][p];
            u64 right = (j == 7) ? nz[p] : zc[j + 1][p];
            u64 a = bb2[p];
            fma2(a, wcp, zc[j][p]);
            fma2(a, wlp, left);
            fma2(a, wrp, right);
            float r0, r1; unpack2(r0, r1, a);
            pool[2 * p]     += fmaxf(r0, 0.f);
            pool[2 * p + 1] += fmaxf(r1, 0.f);
        }
    }

    // butterfly reduce pool over 32 lanes (packed)
    {
        u64 pp[4];
#pragma unroll
        for (int p = 0; p < 4; p++) pp[p] = pack2(pool[2 * p], pool[2 * p + 1]);
#pragma unroll
        for (int s = 16; s > 0; s >>= 1) {
#pragma unroll
            for (int p = 0; p < 4; p++)
                pp[p] = add2(pp[p], __shfl_xor_sync(0xffffffffu, pp[p], s));
        }
        if (lane == 0) {
#pragma unroll
            for (int p = 0; p < 4; p++) {
                float r0, r1; unpack2(r0, r1, pp[p]);
                pooledS[cw + 2 * p]     = r0 * (1.f / 256.f);
                pooledS[cw + 2 * p + 1] = r1 * (1.f / 256.f);
            }
        }
    }
    __syncthreads();

    // ---------------- tail MLPs ----------------
    if (t < HID) {
        const float h0 = heads[2 * b], h1v = heads[2 * b + 1];
        const float bs = body_sizes[b];
        const float fr0 = fruits[2 * b], fr1 = fruits[2 * b + 1];
        float a1 = ba1[t]
                 + h0  * Wa1[0 * HID + t]
                 + h1v * Wa1[1 * HID + t]
                 + bs  * Wa1[2 * HID + t]
                 + fr0 * Wa1[3 * HID + t]
                 + fr1 * Wa1[4 * HID + t];
        auxS[t] = fmaxf(a1, 0.f);
    }
    __syncthreads();

    if (t < HID) {
        float a2 = ba2[t];
#pragma unroll
        for (int k = 0; k < HID; k++) a2 += auxS[k] * Wa2[k * HID + t];
        a2 = fmaxf(a2, 0.f);
        float be = br[t];
#pragma unroll
        for (int k = 0; k < HID; k++) be += pooledS[k] * Wr[k * HID + t];
        cinS[t] = be;
        cinS[HID + t] = a2;
    }
    __syncthreads();

    if (t < FIN) {
        float c = bc[t];
#pragma unroll
        for (int k = 0; k < FIN; k++) c += cinS[k] * Wc[k * FIN + t];
        combS[t] = fmaxf(c, 0.f);
    }
    __syncthreads();

    if (t < 5) {
        float lg = bp[t];
#pragma unroll
        for (int k = 0; k < FIN; k++) lg += combS[k] * Wp[k * 5 + t];
        out[b * 5 + t] = lg;                      // logits [B,5]
    } else if (t == 5) {
        float v = bv[0];
#pragma unroll
        for (int k = 0; k < FIN; k++) v += combS[k] * Wv[k];
        out[B_G * 5 + b] = v;                     // value [B]
    }
}

extern "C" void kernel_launch(void* const* d_in, const int* in_sizes, int n_in,
                              void* d_out, int out_size) {
    const float* x          = (const float*)d_in[0];
    const float* heads      = (const float*)d_in[1];
    const float* body_sizes = (const float*)d_in[2];
    const float* fruits     = (const float*)d_in[3];
    const float* W1  = (const float*)d_in[4];
    const float* b1  = (const float*)d_in[5];
    const float* W2  = (const float*)d_in[6];
    const float* b2  = (const float*)d_in[7];
    const float* Wr  = (const float*)d_in[8];
    const float* br  = (const float*)d_in[9];
    const float* Wa1 = (const float*)d_in[10];
    const float* ba1 = (const float*)d_in[11];
    const float* Wa2 = (const float*)d_in[12];
    const float* ba2 = (const float*)d_in[13];
    const float* Wc  = (const float*)d_in[14];
    const float* bc  = (const float*)d_in[15];
    const float* Wp  = (const float*)d_in[16];
    const float* bp  = (const float*)d_in[17];
    const float* Wv  = (const float*)d_in[18];
    const float* bv  = (const float*)d_in[19];
    // d_in[20] = edge_index, d_in[21] = batch_ids: static chain, unused

    cudaFuncSetAttribute(snake_kernel, cudaFuncAttributeMaxDynamicSharedMemorySize, SMEM_TOTAL);
    float* out = (float*)d_out;
    snake_kernel<<<B_G, 128, SMEM_TOTAL>>>(x, heads, body_sizes, fruits,
                               W1, b1, W2, b2, Wr, br,
                               Wa1, ba1, Wa2, ba2, Wc, bc,
                               Wp, bp, Wv, bv, out);
}